// round 16
// baseline (speedup 1.0000x reference)
#include <cuda_runtime.h>
#include <cuda_fp16.h>
#include <cstdint>

// Problem dims (fixed by the dataset)
#define MDIM 8192
#define KDIM 4096
#define NDIM 4096
#define KT64 (KDIM / 64)   // 64 k-tiles of 64 halves

// ---------------- device scratch (sanctioned: __device__ globals) ----------
// TILE-MAJOR, PRE-SWIZZLED:
//   g_xh    : [m-block(128)][ktile][row 0..127][128B swizzled row]   (64 MB)
//   g_weffh : [n-block(128)][ktile][row 0..127][128B swizzled row]   (32 MB)
__device__ __half g_weffh[(size_t)NDIM * KDIM];
__device__ __half g_xh[(size_t)MDIM * KDIM];

// ---------------- helpers ---------------------------------------------------
__device__ __forceinline__ uint32_t h2_as_u32(__half2 h) {
    return *reinterpret_cast<uint32_t*>(&h);
}
__device__ __forceinline__ uint32_t smem_u32(const void* p) {
    uint32_t a;
    asm("{ .reg .u64 t; cvta.to.shared.u64 t, %1; cvt.u32.u64 %0, t; }" : "=r"(a) : "l"(p));
    return a;
}
__device__ __forceinline__ void ldsm4(uint32_t r[4], uint32_t addr) {
    asm volatile("ldmatrix.sync.aligned.m8n8.x4.shared.b16 {%0,%1,%2,%3}, [%4];"
                 : "=r"(r[0]), "=r"(r[1]), "=r"(r[2]), "=r"(r[3]) : "r"(addr));
}
__device__ __forceinline__ void mma16(float c[4], const uint32_t a[4],
                                      uint32_t b0, uint32_t b1) {
    asm volatile("mma.sync.aligned.m16n8k16.row.col.f32.f16.f16.f32 "
                 "{%0,%1,%2,%3}, {%4,%5,%6,%7}, {%8,%9}, {%0,%1,%2,%3};"
                 : "+f"(c[0]), "+f"(c[1]), "+f"(c[2]), "+f"(c[3])
                 : "r"(a[0]), "r"(a[1]), "r"(a[2]), "r"(a[3]), "r"(b0), "r"(b1));
}
__device__ __forceinline__ void bulkcp(uint32_t dst, const void* src,
                                       uint32_t bytes, uint32_t bar) {
    asm volatile(
        "cp.async.bulk.shared::cta.global.mbarrier::complete_tx::bytes "
        "[%0], [%1], %2, [%3];"
        :: "r"(dst), "l"(src), "r"(bytes), "r"(bar) : "memory");
}
#define MBARRIER_INIT(addr, count) \
    asm volatile("mbarrier.init.shared.b64 [%0], %1;" \
        :: "r"((uint32_t)(addr)), "r"((uint32_t)(count)) : "memory")
#define MBARRIER_EXPECT_TX(addr, bytes) \
    asm volatile("mbarrier.arrive.expect_tx.shared.b64 _, [%0], %1;" \
        :: "r"((uint32_t)(addr)), "r"((uint32_t)(bytes)) : "memory")
#define MBARRIER_ARRIVE(addr) \
    asm volatile("mbarrier.arrive.shared.b64 _, [%0];" \
        :: "r"((uint32_t)(addr)) : "memory")
#define MBARRIER_WAIT_PARITY(mbar_smem_addr, phase_parity) do { \
    uint32_t _mbar = (uint32_t)(mbar_smem_addr); \
    uint32_t _parity = (uint32_t)(phase_parity); \
    uint32_t _done; \
    asm volatile("{\n\t.reg .pred p;\n\t" \
        "mbarrier.try_wait.parity.acquire.cta.shared::cta.b64 p, [%1], %2;\n\t" \
        "selp.b32 %0, 1, 0, p;\n\t}" \
        : "=r"(_done) : "r"(_mbar), "r"(_parity) : "memory"); \
    if (!_done) { \
        asm volatile("{\n\t.reg .pred P1;\n\t" \
            "WAIT_LOOP_%=:\n\t" \
            "mbarrier.try_wait.parity.acquire.cta.shared::cta.b64 P1, [%0], %1, 0x989680;\n\t" \
            "@P1 bra.uni WAIT_DONE_%=;\n\t" \
            "bra.uni WAIT_LOOP_%=;\n\t" \
            "WAIT_DONE_%=:\n\t}" \
            :: "r"(_mbar), "r"(_parity) : "memory"); \
    } \
} while (0)

// ---------------- kernel 1: round x to fp16, tiled+swizzled -----------------
// One thread = one full 16B chunk (8 halves): 2x float4 read, 1x uint4 store.
__global__ void __launch_bounds__(256) round_x_kernel(const float4* __restrict__ x) {
    int i = blockIdx.x * 256 + threadIdx.x;       // 16B-chunk index over [M,K]
    float4 v0 = x[2 * i];
    float4 v1 = x[2 * i + 1];
    int m  = i >> 9;                               // K/8 = 512 chunks per row
    int cc = i & 511;
    int mb = m >> 7, row = m & 127;
    int ktile = cc >> 3;
    int c = cc & 7;
    size_t off = (((size_t)(mb * KT64 + ktile)) * 128 + row) * 128
               + (uint32_t)((c ^ (row & 7)) << 4);
    uint4 w;
    w.x = h2_as_u32(__floats2half2_rn(v0.x, v0.y));
    w.y = h2_as_u32(__floats2half2_rn(v0.z, v0.w));
    w.z = h2_as_u32(__floats2half2_rn(v1.x, v1.y));
    w.w = h2_as_u32(__floats2half2_rn(v1.z, v1.w));
    *reinterpret_cast<uint4*>(reinterpret_cast<char*>(g_xh) + off) = w;
}

// ---------------- kernel 2: W_eff = dequant + lora, tiled+swizzled ----------
__global__ void __launch_bounds__(256) prep_weight_kernel(
    const int* __restrict__ qweight, const float* __restrict__ wscales,
    const float* __restrict__ proj_down, const float* __restrict__ proj_up,
    const float* __restrict__ wtscale)
{
    __shared__ float up_s[16 * 32];
    const int n0 = blockIdx.y * 16;
    const int tid = threadIdx.x;
    #pragma unroll
    for (int j = tid; j < 512; j += 256) {
        int n = j >> 5, r = j & 31;
        up_s[j] = proj_up[(size_t)(n0 + n) * 32 + r];
    }
    __syncthreads();
    const float wt = wtscale[0];
    const int k2 = blockIdx.x * 256 + tid;   // pair index; k = 2*k2, 2*k2+1

    float ae[16], ao[16];
    #pragma unroll
    for (int n = 0; n < 16; n++) { ae[n] = 0.f; ao[n] = 0.f; }
    #pragma unroll 4
    for (int r = 0; r < 32; r++) {
        float2 d2 = *reinterpret_cast<const float2*>(proj_down + (size_t)r * KDIM + 2 * k2);
        #pragma unroll
        for (int n = 0; n < 16; n++) {
            float u = up_s[n * 32 + r];
            ae[n] = fmaf(u, d2.x, ae[n]);
            ao[n] = fmaf(u, d2.y, ao[n]);
        }
    }
    const int g = k2 >> 5;
    const int k = 2 * k2;
    const int ktile = k >> 6;
    const int c = (k >> 3) & 7;
    #pragma unroll
    for (int nn = 0; nn < 16; nn++) {
        int n = n0 + nn;
        int q = qweight[(size_t)n * (KDIM / 2) + k2];
        float s = wscales[(size_t)g * NDIM + n];
        float we = fmaf((float)((q & 15) - 8), s, wt * ae[nn]);
        float wo = fmaf((float)(((q >> 4) & 15) - 8), s, wt * ao[nn]);
        int nb = n >> 7, rowb = n & 127;
        size_t off = (((size_t)(nb * KT64 + ktile)) * 128 + rowb) * 128
                   + (uint32_t)((c ^ (rowb & 7)) << 4) + (k & 7) * 2;
        __half2 hv = __floats2half2_rn(we, wo);
        *reinterpret_cast<__half2*>(reinterpret_cast<char*>(g_weffh) + off) = hv;
    }
}

// ---------------- GEMM: exact R13 mainloop (590us champion), with the ------
// producer block moved to bottom-of-ktile so warp 0's empty-wait follows
// its MMA work instead of preceding it.
#define BM 128
#define BN 128
#define BK 64
#define STAGES 3
#define KTILES KT64                       // 64
#define A_BYTES (BM * BK * 2)             // 16384
#define B_BYTES (BN * BK * 2)             // 16384
#define STAGE_BYTES (A_BYTES + B_BYTES)   // 32768
#define OFF_FULL  0                       // 3 x 8B
#define OFF_EMPTY 24                      // 3 x 8B
#define OFF_STAGE 1024
#define SMEM_TOTAL (OFF_STAGE + STAGES * STAGE_BYTES)   // 99328 -> 2 CTAs/SM

__global__ void __launch_bounds__(128, 2) gemm_fp16_kernel(
    const float* __restrict__ bias, float* __restrict__ out)
{
    extern __shared__ char smem_raw[];
    const uint32_t sbase = smem_u32(smem_raw);
    const uint32_t fullB  = sbase + OFF_FULL;
    const uint32_t emptyB = sbase + OFF_EMPTY;
    const uint32_t stg0   = sbase + OFF_STAGE;

    const int tid  = threadIdx.x;
    const int lane = tid & 31;
    const int warp = tid >> 5;
    const int wm = warp & 1;          // 2 warps in m -> warp tile 64 rows
    const int wn = warp >> 1;         // 2 warps in n -> warp tile 64 cols
    const int m0 = blockIdx.y * BM;
    const int n0 = blockIdx.x * BN;

    const char* gA = reinterpret_cast<const char*>(g_xh)
                   + (size_t)blockIdx.y * KT64 * A_BYTES;
    const char* gB = reinterpret_cast<const char*>(g_weffh)
                   + (size_t)blockIdx.x * KT64 * B_BYTES;

    if (tid == 0) {
        #pragma unroll
        for (int s = 0; s < STAGES; s++) {
            MBARRIER_INIT(fullB  + s * 8, 1);
            MBARRIER_INIT(emptyB + s * 8, 4);   // one arrival per warp
        }
    }
    __syncthreads();   // init visibility (only block-wide sync in the kernel)

    auto issue = [&](int kt, int stg) {
        uint32_t b  = fullB + (uint32_t)(stg * 8);
        uint32_t so = stg0 + (uint32_t)stg * STAGE_BYTES;
        MBARRIER_EXPECT_TX(b, STAGE_BYTES);
        bulkcp(so,           gA + (size_t)kt * A_BYTES, A_BYTES, b);
        bulkcp(so + A_BYTES, gB + (size_t)kt * B_BYTES, B_BYTES, b);
    };
    if (tid == 0) { issue(0, 0); issue(1, 1); }

    // ---- ldmatrix per-lane addressing (R4 geometry) ----
    const int lr = lane & 7;
    const int g1 = (lane >> 3) & 1;
    const int g2 = lane >> 4;
    const uint32_t aOff = (uint32_t)(wm * 64 + lr + (g1 << 3)) * 128;
    const uint32_t bOff = (uint32_t)(wn * 64 + lr + (g2 << 3)) * 128;

    float acc[4][8][4];
    #pragma unroll
    for (int i = 0; i < 4; i++)
        #pragma unroll
        for (int j = 0; j < 8; j++)
            #pragma unroll
            for (int c = 0; c < 4; c++) acc[i][j][c] = 0.f;

    // fragment double buffers (R4 schedule)
    uint32_t fa[2][4][4], fb[2][4][4];
    auto ldsm_step = [&](int buf, int stg, int s) {
        const uint32_t aSt = stg0 + (uint32_t)stg * STAGE_BYTES + aOff;
        const uint32_t bSt = stg0 + (uint32_t)stg * STAGE_BYTES + A_BYTES + bOff;
        const uint32_t xA = (uint32_t)(((2 * s + g2) ^ lr) << 4);
        const uint32_t xB = (uint32_t)(((2 * s + g1) ^ lr) << 4);
        #pragma unroll
        for (int mt = 0; mt < 4; mt++) {
            ldsm4(fa[buf][mt], aSt + mt * 2048 + xA);
            ldsm4(fb[buf][mt], bSt + mt * 2048 + xB);
        }
    };
    auto mma_step = [&](int buf) {
        #pragma unroll
        for (int mt = 0; mt < 4; mt++) {
            #pragma unroll
            for (int p = 0; p < 4; p++) {
                mma16(acc[mt][2 * p],     fa[buf][mt], fb[buf][p][0], fb[buf][p][1]);
                mma16(acc[mt][2 * p + 1], fa[buf][mt], fb[buf][p][2], fb[buf][p][3]);
            }
        }
    };

    int st = 0, phase = 0;        // read cursor (full bars)
    int wst = 2;                  // write cursor (issue distance 2)
    for (int kt = 0; kt < KTILES; kt++) {
        // -------- consumers: wait data, compute, release stage --------
        MBARRIER_WAIT_PARITY(fullB + st * 8, phase);

        ldsm_step(0, st, 0);
        #pragma unroll
        for (int s = 0; s < 4; s++) {
            const int cur = s & 1;
            if (s < 3) {
                ldsm_step(cur ^ 1, st, s + 1);   // prefetch next step's fragments
                mma_step(cur);
            } else {
                mma_step(cur);                    // last MMAs cover next wait
            }
        }
        // all of this warp's reads of stage st are complete (ldmatrix is
        // warp-synchronous) -> lane 0 releases the stage
        if (lane == 0) MBARRIER_ARRIVE(emptyB + st * 8);

        // -------- producer (moved to bottom): WAR-wait, re-issue --------
        // warp 0 has already issued all its MMAs for this ktile; its wait
        // on laggard warps' empty-arrivals no longer delays the tensor pipe.
        if (tid == 0 && kt + 2 < KTILES) {
            if (kt >= 1) {
                int epar = ((kt - 1) / 3) & 1;
                MBARRIER_WAIT_PARITY(emptyB + wst * 8, epar);
            }
            issue(kt + 2, wst);
        }
        if (++wst == STAGES) wst = 0;

        if (++st == STAGES) { st = 0; phase ^= 1; }
    }

    // ---- epilogue: add bias, store float2 ----
    const int mrow = m0 + wm * 64 + (lane >> 2);
    const int ncol = n0 + wn * 64 + 2 * (lane & 3);
    float2 bv[8];
    #pragma unroll
    for (int nt = 0; nt < 8; nt++)
        bv[nt] = *reinterpret_cast<const float2*>(bias + ncol + nt * 8);

    #pragma unroll
    for (int mt = 0; mt < 4; mt++) {
        float* r0 = out + (size_t)(mrow + mt * 16) * NDIM + ncol;
        float* r1 = out + (size_t)(mrow + mt * 16 + 8) * NDIM + ncol;
        #pragma unroll
        for (int nt = 0; nt < 8; nt++) {
            float2 v0 = make_float2(acc[mt][nt][0] + bv[nt].x, acc[mt][nt][1] + bv[nt].y);
            float2 v1 = make_float2(acc[mt][nt][2] + bv[nt].x, acc[mt][nt][3] + bv[nt].y);
            *reinterpret_cast<float2*>(r0 + nt * 8) = v0;
            *reinterpret_cast<float2*>(r1 + nt * 8) = v1;
        }
    }
}

// ---------------- launch ----------------------------------------------------
extern "C" void kernel_launch(void* const* d_in, const int* in_sizes, int n_in,
                              void* d_out, int out_size) {
    const float* x    = (const float*)d_in[0];
    const int*   qw   = (const int*)d_in[1];
    const float* ws   = (const float*)d_in[2];
    const float* pd   = (const float*)d_in[3];
    const float* pu   = (const float*)d_in[4];
    const float* wt   = (const float*)d_in[5];
    const float* bias = (const float*)d_in[6];
    float* out = (float*)d_out;

    // separate prologue launches (fused version twice rejected)
    round_x_kernel<<<(MDIM * KDIM / 8) / 256, 256>>>((const float4*)x);
    prep_weight_kernel<<<dim3(KDIM / 512, NDIM / 16), 256>>>(qw, ws, pd, pu, wt);

    // main GEMM (R13 mainloop + bottom-of-loop producer)
    cudaFuncSetAttribute(gemm_fp16_kernel, cudaFuncAttributeMaxDynamicSharedMemorySize, SMEM_TOTAL);
    gemm_fp16_kernel<<<dim3(NDIM / BN, MDIM / BM), 128, SMEM_TOTAL>>>(bias, out);
}

// round 17
// speedup vs baseline: 1.4997x; 1.4997x over previous
#include <cuda_runtime.h>
#include <cuda_fp16.h>
#include <cstdint>

// Problem dims (fixed by the dataset)
#define MDIM 8192
#define KDIM 4096
#define NDIM 4096
#define KT64 (KDIM / 64)   // 64 k-tiles of 64 halves

// ---------------- device scratch (sanctioned: __device__ globals) ----------
// TILE-MAJOR, PRE-SWIZZLED:
//   g_xh    : [m-block(128)][ktile][row 0..127][128B swizzled row]   (64 MB)
//   g_weffh : [n-block(128)][ktile][row 0..127][128B swizzled row]   (32 MB)
__device__ __half g_weffh[(size_t)NDIM * KDIM];
__device__ __half g_xh[(size_t)MDIM * KDIM];

// ---------------- helpers ---------------------------------------------------
__device__ __forceinline__ uint32_t h2_as_u32(__half2 h) {
    return *reinterpret_cast<uint32_t*>(&h);
}
__device__ __forceinline__ uint32_t smem_u32(const void* p) {
    uint32_t a;
    asm("{ .reg .u64 t; cvta.to.shared.u64 t, %1; cvt.u32.u64 %0, t; }" : "=r"(a) : "l"(p));
    return a;
}
__device__ __forceinline__ void ldsm4(uint32_t r[4], uint32_t addr) {
    asm volatile("ldmatrix.sync.aligned.m8n8.x4.shared.b16 {%0,%1,%2,%3}, [%4];"
                 : "=r"(r[0]), "=r"(r[1]), "=r"(r[2]), "=r"(r[3]) : "r"(addr));
}
__device__ __forceinline__ void mma16(float c[4], const uint32_t a[4],
                                      uint32_t b0, uint32_t b1) {
    asm volatile("mma.sync.aligned.m16n8k16.row.col.f32.f16.f16.f32 "
                 "{%0,%1,%2,%3}, {%4,%5,%6,%7}, {%8,%9}, {%0,%1,%2,%3};"
                 : "+f"(c[0]), "+f"(c[1]), "+f"(c[2]), "+f"(c[3])
                 : "r"(a[0]), "r"(a[1]), "r"(a[2]), "r"(a[3]), "r"(b0), "r"(b1));
}
__device__ __forceinline__ void bulkcp(uint32_t dst, const void* src,
                                       uint32_t bytes, uint32_t bar) {
    asm volatile(
        "cp.async.bulk.shared::cta.global.mbarrier::complete_tx::bytes "
        "[%0], [%1], %2, [%3];"
        :: "r"(dst), "l"(src), "r"(bytes), "r"(bar) : "memory");
}
#define MBARRIER_INIT(addr, count) \
    asm volatile("mbarrier.init.shared.b64 [%0], %1;" \
        :: "r"((uint32_t)(addr)), "r"((uint32_t)(count)) : "memory")
#define MBARRIER_EXPECT_TX(addr, bytes) \
    asm volatile("mbarrier.arrive.expect_tx.shared.b64 _, [%0], %1;" \
        :: "r"((uint32_t)(addr)), "r"((uint32_t)(bytes)) : "memory")
#define MBARRIER_ARRIVE(addr) \
    asm volatile("mbarrier.arrive.shared.b64 _, [%0];" \
        :: "r"((uint32_t)(addr)) : "memory")
#define MBARRIER_WAIT_PARITY(mbar_smem_addr, phase_parity) do { \
    uint32_t _mbar = (uint32_t)(mbar_smem_addr); \
    uint32_t _parity = (uint32_t)(phase_parity); \
    uint32_t _done; \
    asm volatile("{\n\t.reg .pred p;\n\t" \
        "mbarrier.try_wait.parity.acquire.cta.shared::cta.b64 p, [%1], %2;\n\t" \
        "selp.b32 %0, 1, 0, p;\n\t}" \
        : "=r"(_done) : "r"(_mbar), "r"(_parity) : "memory"); \
    if (!_done) { \
        asm volatile("{\n\t.reg .pred P1;\n\t" \
            "WAIT_LOOP_%=:\n\t" \
            "mbarrier.try_wait.parity.acquire.cta.shared::cta.b64 P1, [%0], %1, 0x989680;\n\t" \
            "@P1 bra.uni WAIT_DONE_%=;\n\t" \
            "bra.uni WAIT_LOOP_%=;\n\t" \
            "WAIT_DONE_%=:\n\t}" \
            :: "r"(_mbar), "r"(_parity) : "memory"); \
    } \
} while (0)

// ---------------- kernel 1: round x to fp16, tiled+swizzled -----------------
// One thread = one full 16B chunk (8 halves): 2x float4 read, 1x uint4 store.
// (Measured 29.4us vs 31.5us for the 8B-store variant.)
__global__ void __launch_bounds__(256) round_x_kernel(const float4* __restrict__ x) {
    int i = blockIdx.x * 256 + threadIdx.x;       // 16B-chunk index over [M,K]
    float4 v0 = x[2 * i];
    float4 v1 = x[2 * i + 1];
    int m  = i >> 9;                               // K/8 = 512 chunks per row
    int cc = i & 511;
    int mb = m >> 7, row = m & 127;
    int ktile = cc >> 3;
    int c = cc & 7;
    size_t off = (((size_t)(mb * KT64 + ktile)) * 128 + row) * 128
               + (uint32_t)((c ^ (row & 7)) << 4);
    uint4 w;
    w.x = h2_as_u32(__floats2half2_rn(v0.x, v0.y));
    w.y = h2_as_u32(__floats2half2_rn(v0.z, v0.w));
    w.z = h2_as_u32(__floats2half2_rn(v1.x, v1.y));
    w.w = h2_as_u32(__floats2half2_rn(v1.z, v1.w));
    *reinterpret_cast<uint4*>(reinterpret_cast<char*>(g_xh) + off) = w;
}

// ---------------- kernel 2: W_eff = dequant + lora, tiled+swizzled ----------
__global__ void __launch_bounds__(256) prep_weight_kernel(
    const int* __restrict__ qweight, const float* __restrict__ wscales,
    const float* __restrict__ proj_down, const float* __restrict__ proj_up,
    const float* __restrict__ wtscale)
{
    __shared__ float up_s[16 * 32];
    const int n0 = blockIdx.y * 16;
    const int tid = threadIdx.x;
    #pragma unroll
    for (int j = tid; j < 512; j += 256) {
        int n = j >> 5, r = j & 31;
        up_s[j] = proj_up[(size_t)(n0 + n) * 32 + r];
    }
    __syncthreads();
    const float wt = wtscale[0];
    const int k2 = blockIdx.x * 256 + tid;   // pair index; k = 2*k2, 2*k2+1

    float ae[16], ao[16];
    #pragma unroll
    for (int n = 0; n < 16; n++) { ae[n] = 0.f; ao[n] = 0.f; }
    #pragma unroll 4
    for (int r = 0; r < 32; r++) {
        float2 d2 = *reinterpret_cast<const float2*>(proj_down + (size_t)r * KDIM + 2 * k2);
        #pragma unroll
        for (int n = 0; n < 16; n++) {
            float u = up_s[n * 32 + r];
            ae[n] = fmaf(u, d2.x, ae[n]);
            ao[n] = fmaf(u, d2.y, ao[n]);
        }
    }
    const int g = k2 >> 5;
    const int k = 2 * k2;
    const int ktile = k >> 6;
    const int c = (k >> 3) & 7;
    #pragma unroll
    for (int nn = 0; nn < 16; nn++) {
        int n = n0 + nn;
        int q = qweight[(size_t)n * (KDIM / 2) + k2];
        float s = wscales[(size_t)g * NDIM + n];
        float we = fmaf((float)((q & 15) - 8), s, wt * ae[nn]);
        float wo = fmaf((float)(((q >> 4) & 15) - 8), s, wt * ao[nn]);
        int nb = n >> 7, rowb = n & 127;
        size_t off = (((size_t)(nb * KT64 + ktile)) * 128 + rowb) * 128
                   + (uint32_t)((c ^ (rowb & 7)) << 4) + (k & 7) * 2;
        __half2 hv = __floats2half2_rn(we, wo);
        *reinterpret_cast<__half2*>(reinterpret_cast<char*>(g_weffh) + off) = hv;
    }
}

// ---------------- GEMM: EXACT R13 champion (590us) -------------------------
// 128x128 tile, 64x64 warp tiles, 2 CTAs/SM, bulk-fed, fragment
// double-buffered, full/empty mbarrier ring, producer at TOP of ktile.
#define BM 128
#define BN 128
#define BK 64
#define STAGES 3
#define KTILES KT64                       // 64
#define A_BYTES (BM * BK * 2)             // 16384
#define B_BYTES (BN * BK * 2)             // 16384
#define STAGE_BYTES (A_BYTES + B_BYTES)   // 32768
#define OFF_FULL  0                       // 3 x 8B
#define OFF_EMPTY 24                      // 3 x 8B
#define OFF_STAGE 1024
#define SMEM_TOTAL (OFF_STAGE + STAGES * STAGE_BYTES)   // 99328 -> 2 CTAs/SM

__global__ void __launch_bounds__(128, 2) gemm_fp16_kernel(
    const float* __restrict__ bias, float* __restrict__ out)
{
    extern __shared__ char smem_raw[];
    const uint32_t sbase = smem_u32(smem_raw);
    const uint32_t fullB  = sbase + OFF_FULL;
    const uint32_t emptyB = sbase + OFF_EMPTY;
    const uint32_t stg0   = sbase + OFF_STAGE;

    const int tid  = threadIdx.x;
    const int lane = tid & 31;
    const int warp = tid >> 5;
    const int wm = warp & 1;          // 2 warps in m -> warp tile 64 rows
    const int wn = warp >> 1;         // 2 warps in n -> warp tile 64 cols
    const int m0 = blockIdx.y * BM;
    const int n0 = blockIdx.x * BN;

    const char* gA = reinterpret_cast<const char*>(g_xh)
                   + (size_t)blockIdx.y * KT64 * A_BYTES;
    const char* gB = reinterpret_cast<const char*>(g_weffh)
                   + (size_t)blockIdx.x * KT64 * B_BYTES;

    if (tid == 0) {
        #pragma unroll
        for (int s = 0; s < STAGES; s++) {
            MBARRIER_INIT(fullB  + s * 8, 1);
            MBARRIER_INIT(emptyB + s * 8, 4);   // one arrival per warp
        }
    }
    __syncthreads();   // init visibility (only block-wide sync in the kernel)

    auto issue = [&](int kt, int stg) {
        uint32_t b  = fullB + (uint32_t)(stg * 8);
        uint32_t so = stg0 + (uint32_t)stg * STAGE_BYTES;
        MBARRIER_EXPECT_TX(b, STAGE_BYTES);
        bulkcp(so,           gA + (size_t)kt * A_BYTES, A_BYTES, b);
        bulkcp(so + A_BYTES, gB + (size_t)kt * B_BYTES, B_BYTES, b);
    };
    if (tid == 0) { issue(0, 0); issue(1, 1); }

    // ---- ldmatrix per-lane addressing (R4 geometry) ----
    const int lr = lane & 7;
    const int g1 = (lane >> 3) & 1;
    const int g2 = lane >> 4;
    const uint32_t aOff = (uint32_t)(wm * 64 + lr + (g1 << 3)) * 128;
    const uint32_t bOff = (uint32_t)(wn * 64 + lr + (g2 << 3)) * 128;

    float acc[4][8][4];
    #pragma unroll
    for (int i = 0; i < 4; i++)
        #pragma unroll
        for (int j = 0; j < 8; j++)
            #pragma unroll
            for (int c = 0; c < 4; c++) acc[i][j][c] = 0.f;

    // fragment double buffers (R4 schedule)
    uint32_t fa[2][4][4], fb[2][4][4];
    auto ldsm_step = [&](int buf, int stg, int s) {
        const uint32_t aSt = stg0 + (uint32_t)stg * STAGE_BYTES + aOff;
        const uint32_t bSt = stg0 + (uint32_t)stg * STAGE_BYTES + A_BYTES + bOff;
        const uint32_t xA = (uint32_t)(((2 * s + g2) ^ lr) << 4);
        const uint32_t xB = (uint32_t)(((2 * s + g1) ^ lr) << 4);
        #pragma unroll
        for (int mt = 0; mt < 4; mt++) {
            ldsm4(fa[buf][mt], aSt + mt * 2048 + xA);
            ldsm4(fb[buf][mt], bSt + mt * 2048 + xB);
        }
    };
    auto mma_step = [&](int buf) {
        #pragma unroll
        for (int mt = 0; mt < 4; mt++) {
            #pragma unroll
            for (int p = 0; p < 4; p++) {
                mma16(acc[mt][2 * p],     fa[buf][mt], fb[buf][p][0], fb[buf][p][1]);
                mma16(acc[mt][2 * p + 1], fa[buf][mt], fb[buf][p][2], fb[buf][p][3]);
            }
        }
    };

    int st = 0, phase = 0;        // read cursor (full bars)
    int wst = 2;                  // write cursor (issue distance 2)
    for (int kt = 0; kt < KTILES; kt++) {
        // -------- producer: WAR-wait on empty, then re-issue --------
        if (tid == 0 && kt + 2 < KTILES) {
            if (kt >= 1) {
                int epar = ((kt - 1) / 3) & 1;
                MBARRIER_WAIT_PARITY(emptyB + wst * 8, epar);
            }
            issue(kt + 2, wst);
        }
        if (++wst == STAGES) wst = 0;

        // -------- consumers: wait data, compute, release stage --------
        MBARRIER_WAIT_PARITY(fullB + st * 8, phase);

        ldsm_step(0, st, 0);
        #pragma unroll
        for (int s = 0; s < 4; s++) {
            const int cur = s & 1;
            if (s < 3) {
                ldsm_step(cur ^ 1, st, s + 1);   // prefetch next step's fragments
                mma_step(cur);
            } else {
                mma_step(cur);                    // last MMAs cover next wait
            }
        }
        // all of this warp's reads of stage st are complete (ldmatrix is
        // warp-synchronous) -> lane 0 releases the stage
        if (lane == 0) MBARRIER_ARRIVE(emptyB + st * 8);

        if (++st == STAGES) { st = 0; phase ^= 1; }
    }

    // ---- epilogue: add bias, store float2 ----
    const int mrow = m0 + wm * 64 + (lane >> 2);
    const int ncol = n0 + wn * 64 + 2 * (lane & 3);
    float2 bv[8];
    #pragma unroll
    for (int nt = 0; nt < 8; nt++)
        bv[nt] = *reinterpret_cast<const float2*>(bias + ncol + nt * 8);

    #pragma unroll
    for (int mt = 0; mt < 4; mt++) {
        float* r0 = out + (size_t)(mrow + mt * 16) * NDIM + ncol;
        float* r1 = out + (size_t)(mrow + mt * 16 + 8) * NDIM + ncol;
        #pragma unroll
        for (int nt = 0; nt < 8; nt++) {
            float2 v0 = make_float2(acc[mt][nt][0] + bv[nt].x, acc[mt][nt][1] + bv[nt].y);
            float2 v1 = make_float2(acc[mt][nt][2] + bv[nt].x, acc[mt][nt][3] + bv[nt].y);
            *reinterpret_cast<float2*>(r0 + nt * 8) = v0;
            *reinterpret_cast<float2*>(r1 + nt * 8) = v1;
        }
    }
}

// ---------------- launch ----------------------------------------------------
extern "C" void kernel_launch(void* const* d_in, const int* in_sizes, int n_in,
                              void* d_out, int out_size) {
    const float* x    = (const float*)d_in[0];
    const int*   qw   = (const int*)d_in[1];
    const float* ws   = (const float*)d_in[2];
    const float* pd   = (const float*)d_in[3];
    const float* pu   = (const float*)d_in[4];
    const float* wt   = (const float*)d_in[5];
    const float* bias = (const float*)d_in[6];
    float* out = (float*)d_out;

    // separate prologue launches (fused version twice rejected)
    round_x_kernel<<<(MDIM * KDIM / 8) / 256, 256>>>((const float4*)x);
    prep_weight_kernel<<<dim3(KDIM / 512, NDIM / 16), 256>>>(qw, ws, pd, pu, wt);

    // main GEMM (exact R13 champion)
    cudaFuncSetAttribute(gemm_fp16_kernel, cudaFuncAttributeMaxDynamicSharedMemorySize, SMEM_TOTAL);
    gemm_fp16_kernel<<<dim3(NDIM / BN, MDIM / BM), 128, SMEM_TOTAL>>>(bias, out);
}